// round 1
// baseline (speedup 1.0000x reference)
#include <cuda_runtime.h>

// Problem constants
#define T_DIM 2048
#define B_DIM 2
#define E_DIM 1024
#define H_DIM 16
#define HD_DIM 64
#define S_DIM 2048
#define MB_DIM (T_DIM * B_DIM)          // 4096 rows for projection GEMMs
#define LDB_KV (B_DIM * E_DIM)          // 2048: row stride (over t or s) in (T,B,E) tensors

// Static device scratch (allocation-free rule: __device__ globals)
__device__ float g_q[(size_t)MB_DIM * E_DIM];
__device__ float g_k[(size_t)MB_DIM * E_DIM];
__device__ float g_v[(size_t)MB_DIM * E_DIM];
__device__ float g_ctx[(size_t)MB_DIM * E_DIM];
__device__ float g_scores[(size_t)B_DIM * H_DIM * T_DIM * S_DIM];  // 512 MB

// ---------------------------------------------------------------------------
// Generic C = A @ W^T + bias   (A: MxK row-major, W: NxK row-major)
// Tile: BM=BN=64, BK=16, 256 threads, 4x4 per-thread register tile.
// ---------------------------------------------------------------------------
__global__ void __launch_bounds__(256) gemm_xwT(
    const float* __restrict__ A, const float* __restrict__ W,
    const float* __restrict__ bias, float* __restrict__ C,
    int M, int N, int K)
{
    __shared__ float As[16][64];
    __shared__ float Ws[16][64];

    const int tid = threadIdx.x;
    const int tx = tid & 15;           // n direction (x4)
    const int ty = tid >> 4;           // m direction (x4)
    const int m0 = blockIdx.y * 64;
    const int n0 = blockIdx.x * 64;

    const int lr = tid >> 2;           // 0..63 : row within tile
    const int lc = (tid & 3) * 4;      // 0,4,8,12 : k offset

    const float* Ap = A + (size_t)(m0 + lr) * K + lc;
    const float* Wp = W + (size_t)(n0 + lr) * K + lc;

    float acc[4][4];
#pragma unroll
    for (int i = 0; i < 4; i++)
#pragma unroll
        for (int j = 0; j < 4; j++) acc[i][j] = 0.f;

    for (int k0 = 0; k0 < K; k0 += 16) {
        float4 a = *(const float4*)(Ap + k0);
        float4 w = *(const float4*)(Wp + k0);
        As[lc + 0][lr] = a.x; As[lc + 1][lr] = a.y; As[lc + 2][lr] = a.z; As[lc + 3][lr] = a.w;
        Ws[lc + 0][lr] = w.x; Ws[lc + 1][lr] = w.y; Ws[lc + 2][lr] = w.z; Ws[lc + 3][lr] = w.w;
        __syncthreads();
#pragma unroll
        for (int kk = 0; kk < 16; kk++) {
            float4 av = *(const float4*)(&As[kk][ty * 4]);
            float4 wv = *(const float4*)(&Ws[kk][tx * 4]);
            float af[4] = {av.x, av.y, av.z, av.w};
            float wf[4] = {wv.x, wv.y, wv.z, wv.w};
#pragma unroll
            for (int i = 0; i < 4; i++)
#pragma unroll
                for (int j = 0; j < 4; j++) acc[i][j] += af[i] * wf[j];
        }
        __syncthreads();
    }

#pragma unroll
    for (int i = 0; i < 4; i++) {
        float* Cr = C + (size_t)(m0 + ty * 4 + i) * N + n0 + tx * 4;
#pragma unroll
        for (int j = 0; j < 4; j++)
            Cr[j] = acc[i][j] + bias[n0 + tx * 4 + j];
    }
}

// ---------------------------------------------------------------------------
// scores[b,h,t,s] = 0.125 * sum_d q[t,b,h,d] * k[s,b,h,d]
// Batched GEMM A @ B^T, z = b*H + h, K = 64.
// ---------------------------------------------------------------------------
__global__ void __launch_bounds__(256) scores_gemm(
    const float* __restrict__ Q, const float* __restrict__ Kp,
    float* __restrict__ Sout)
{
    const int z = blockIdx.z;
    const int b = z / H_DIM, h = z % H_DIM;
    const float* A  = Q  + (size_t)b * E_DIM + h * HD_DIM;  // row stride LDB_KV
    const float* Bm = Kp + (size_t)b * E_DIM + h * HD_DIM;  // row stride LDB_KV
    float* C = Sout + (size_t)z * T_DIM * S_DIM;

    __shared__ float As[16][64];
    __shared__ float Bs[16][64];

    const int tid = threadIdx.x;
    const int tx = tid & 15;
    const int ty = tid >> 4;
    const int m0 = blockIdx.y * 64;
    const int n0 = blockIdx.x * 64;
    const int lr = tid >> 2;
    const int lc = (tid & 3) * 4;

    float acc[4][4];
#pragma unroll
    for (int i = 0; i < 4; i++)
#pragma unroll
        for (int j = 0; j < 4; j++) acc[i][j] = 0.f;

    for (int k0 = 0; k0 < HD_DIM; k0 += 16) {
        float4 a = *(const float4*)(A  + (size_t)(m0 + lr) * LDB_KV + k0 + lc);
        float4 w = *(const float4*)(Bm + (size_t)(n0 + lr) * LDB_KV + k0 + lc);
        As[lc + 0][lr] = a.x; As[lc + 1][lr] = a.y; As[lc + 2][lr] = a.z; As[lc + 3][lr] = a.w;
        Bs[lc + 0][lr] = w.x; Bs[lc + 1][lr] = w.y; Bs[lc + 2][lr] = w.z; Bs[lc + 3][lr] = w.w;
        __syncthreads();
#pragma unroll
        for (int kk = 0; kk < 16; kk++) {
            float4 av = *(const float4*)(&As[kk][ty * 4]);
            float4 wv = *(const float4*)(&Bs[kk][tx * 4]);
            float af[4] = {av.x, av.y, av.z, av.w};
            float wf[4] = {wv.x, wv.y, wv.z, wv.w};
#pragma unroll
            for (int i = 0; i < 4; i++)
#pragma unroll
                for (int j = 0; j < 4; j++) acc[i][j] += af[i] * wf[j];
        }
        __syncthreads();
    }

#pragma unroll
    for (int i = 0; i < 4; i++) {
        float* Cr = C + (size_t)(m0 + ty * 4 + i) * S_DIM + n0 + tx * 4;
#pragma unroll
        for (int j = 0; j < 4; j++)
            Cr[j] = 0.125f * acc[i][j];
    }
}

// ---------------------------------------------------------------------------
// Per-(b,t) row softmax over s for all 16 heads, in place; also produce
// avg_w[b,t,s] = mean_h attn. 256 threads, 8 s-values per thread.
// ---------------------------------------------------------------------------
__global__ void __launch_bounds__(256) softmax_avg(
    float* __restrict__ scores, float* __restrict__ avgw)
{
    const int t = blockIdx.x;
    const int b = blockIdx.y;
    const int tid = threadIdx.x;
    __shared__ float red[8];

    float avg[8];
#pragma unroll
    for (int i = 0; i < 8; i++) avg[i] = 0.f;

    for (int h = 0; h < H_DIM; h++) {
        float* row = scores + (((size_t)(b * H_DIM + h)) * T_DIM + t) * S_DIM;
        float v[8];
        float m = -1e30f;
#pragma unroll
        for (int i = 0; i < 8; i++) {
            v[i] = row[tid + i * 256];
            m = fmaxf(m, v[i]);
        }
#pragma unroll
        for (int o = 16; o; o >>= 1) m = fmaxf(m, __shfl_xor_sync(0xffffffffu, m, o));
        if ((tid & 31) == 0) red[tid >> 5] = m;
        __syncthreads();
        float M = red[0];
#pragma unroll
        for (int i = 1; i < 8; i++) M = fmaxf(M, red[i]);
        __syncthreads();

        float s = 0.f;
#pragma unroll
        for (int i = 0; i < 8; i++) {
            v[i] = __expf(v[i] - M);
            s += v[i];
        }
#pragma unroll
        for (int o = 16; o; o >>= 1) s += __shfl_xor_sync(0xffffffffu, s, o);
        if ((tid & 31) == 0) red[tid >> 5] = s;
        __syncthreads();
        float Z = red[0];
#pragma unroll
        for (int i = 1; i < 8; i++) Z += red[i];
        const float inv = 1.f / Z;
#pragma unroll
        for (int i = 0; i < 8; i++) {
            v[i] *= inv;
            row[tid + i * 256] = v[i];
            avg[i] += v[i];
        }
        __syncthreads();
    }

    float* arow = avgw + ((size_t)b * T_DIM + t) * S_DIM;
    const float invH = 1.f / (float)H_DIM;
#pragma unroll
    for (int i = 0; i < 8; i++) arow[tid + i * 256] = avg[i] * invH;
}

// ---------------------------------------------------------------------------
// ctx[t,b,h,d] = sum_s attn[b,h,t,s] * v[s,b,h,d]    (batched A @ B)
// M = T (2048), N = 64 (one tile), K = S (2048).
// ---------------------------------------------------------------------------
__global__ void __launch_bounds__(256) av_gemm(
    const float* __restrict__ Attn, const float* __restrict__ V,
    float* __restrict__ Ctx)
{
    const int z = blockIdx.z;
    const int b = z / H_DIM, h = z % H_DIM;
    const float* A  = Attn + (size_t)z * T_DIM * S_DIM;        // lda = S_DIM
    const float* Bm = V    + (size_t)b * E_DIM + h * HD_DIM;   // row stride LDB_KV
    float* C = Ctx + (size_t)b * E_DIM + h * HD_DIM;           // row stride LDB_KV

    __shared__ float As[16][64];
    __shared__ float Bs[16][64];

    const int tid = threadIdx.x;
    const int tx = tid & 15;
    const int ty = tid >> 4;
    const int m0 = blockIdx.y * 64;

    const int lr = tid >> 2;          // A: 0..63 m-row
    const int lc = (tid & 3) * 4;     // A: k offset
    const int kr = tid >> 4;          // B: 0..15 k-row
    const int nc = (tid & 15) * 4;    // B: n offset

    float acc[4][4];
#pragma unroll
    for (int i = 0; i < 4; i++)
#pragma unroll
        for (int j = 0; j < 4; j++) acc[i][j] = 0.f;

    for (int k0 = 0; k0 < S_DIM; k0 += 16) {
        float4 a = *(const float4*)(A + (size_t)(m0 + lr) * S_DIM + k0 + lc);
        As[lc + 0][lr] = a.x; As[lc + 1][lr] = a.y; As[lc + 2][lr] = a.z; As[lc + 3][lr] = a.w;
        float4 bvv = *(const float4*)(Bm + (size_t)(k0 + kr) * LDB_KV + nc);
        *(float4*)(&Bs[kr][nc]) = bvv;
        __syncthreads();
#pragma unroll
        for (int kk = 0; kk < 16; kk++) {
            float4 av = *(const float4*)(&As[kk][ty * 4]);
            float4 wv = *(const float4*)(&Bs[kk][tx * 4]);
            float af[4] = {av.x, av.y, av.z, av.w};
            float wf[4] = {wv.x, wv.y, wv.z, wv.w};
#pragma unroll
            for (int i = 0; i < 4; i++)
#pragma unroll
                for (int j = 0; j < 4; j++) acc[i][j] += af[i] * wf[j];
        }
        __syncthreads();
    }

#pragma unroll
    for (int i = 0; i < 4; i++) {
        float* Cr = C + (size_t)(m0 + ty * 4 + i) * LDB_KV + tx * 4;
#pragma unroll
        for (int j = 0; j < 4; j++)
            Cr[j] = acc[i][j];
    }
}

// ---------------------------------------------------------------------------
extern "C" void kernel_launch(void* const* d_in, const int* in_sizes, int n_in,
                              void* d_out, int out_size)
{
    const float* query = (const float*)d_in[0];
    const float* key   = (const float*)d_in[1];
    const float* value = (const float*)d_in[2];
    const float* Wq = (const float*)d_in[3];
    const float* bq = (const float*)d_in[4];
    const float* Wk = (const float*)d_in[5];
    const float* bk = (const float*)d_in[6];
    const float* Wv = (const float*)d_in[7];
    const float* bv = (const float*)d_in[8];
    const float* Wo = (const float*)d_in[9];
    const float* bo = (const float*)d_in[10];

    float* out  = (float*)d_out;                               // (T,B,E)
    float* avgw = out + (size_t)MB_DIM * E_DIM;                // (B,T,S)

    float *q, *k, *v, *ctx, *sc;
    cudaGetSymbolAddress((void**)&q,   g_q);
    cudaGetSymbolAddress((void**)&k,   g_k);
    cudaGetSymbolAddress((void**)&v,   g_v);
    cudaGetSymbolAddress((void**)&ctx, g_ctx);
    cudaGetSymbolAddress((void**)&sc,  g_scores);

    dim3 gp(E_DIM / 64, MB_DIM / 64);          // (16, 64)
    gemm_xwT<<<gp, 256>>>(query, Wq, bq, q, MB_DIM, E_DIM, E_DIM);
    gemm_xwT<<<gp, 256>>>(key,   Wk, bk, k, MB_DIM, E_DIM, E_DIM);
    gemm_xwT<<<gp, 256>>>(value, Wv, bv, v, MB_DIM, E_DIM, E_DIM);

    dim3 gs(S_DIM / 64, T_DIM / 64, B_DIM * H_DIM);  // (32, 32, 32)
    scores_gemm<<<gs, 256>>>(q, k, sc);

    dim3 gm(T_DIM, B_DIM);                     // (2048, 2)
    softmax_avg<<<gm, 256>>>(sc, avgw);

    dim3 ga(1, T_DIM / 64, B_DIM * H_DIM);     // (1, 32, 32)
    av_gemm<<<ga, 256>>>(sc, v, ctx);

    gemm_xwT<<<gp, 256>>>(ctx, Wo, bo, out, MB_DIM, E_DIM, E_DIM);
}

// round 3
// speedup vs baseline: 1.8758x; 1.8758x over previous
#include <cuda_runtime.h>
#include <cstdint>

#define T_DIM 2048
#define B_DIM 2
#define E_DIM 1024
#define H_DIM 16
#define HD_DIM 64
#define S_DIM 2048
#define MB_DIM (T_DIM * B_DIM)     // 4096
#define LDQ (B_DIM * E_DIM)        // 2048

// Static device scratch
__device__ float g_q[(size_t)MB_DIM * E_DIM];
__device__ float g_k[(size_t)MB_DIM * E_DIM];
__device__ float g_v[(size_t)MB_DIM * E_DIM];
__device__ float g_vt[(size_t)B_DIM * H_DIM * HD_DIM * S_DIM];
__device__ float g_ctx[(size_t)MB_DIM * E_DIM];
__device__ float g_scores[(size_t)B_DIM * H_DIM * T_DIM * S_DIM];

__device__ __forceinline__ uint32_t tf32u(float x) {
    uint32_t u;
    asm("cvt.rna.tf32.f32 %0, %1;" : "=r"(u) : "f"(x));
    return u;
}

__device__ __forceinline__ void mma_tf32(float c[4], const uint32_t a[4], const uint32_t b[2]) {
    asm volatile(
        "mma.sync.aligned.m16n8k8.row.col.f32.tf32.tf32.f32 "
        "{%0,%1,%2,%3}, {%4,%5,%6,%7}, {%8,%9}, {%0,%1,%2,%3};"
        : "+f"(c[0]), "+f"(c[1]), "+f"(c[2]), "+f"(c[3])
        : "r"(a[0]), "r"(a[1]), "r"(a[2]), "r"(a[3]), "r"(b[0]), "r"(b[1]));
}

// ---------------------------------------------------------------------------
// tf32 mma.sync GEMM core. C[m][n] = alpha * sum_k A[m][k]*B[n][k] (+bias[n])
// BM=128, BK=32, 256 threads (8 warps).
// ---------------------------------------------------------------------------
template <int BN, int WARPS_M, int WARPS_N>
__device__ __forceinline__ void mm_core(
    const float* __restrict__ A, int lda,
    const float* __restrict__ B, int ldb,
    float* __restrict__ C, int ldc,
    const float* __restrict__ bias, float alpha, int K)
{
    constexpr int BM = 128, BK = 32;
    constexpr int WM = BM / WARPS_M, WN = BN / WARPS_N;
    constexpr int MF = WM / 16, NF = WN / 8;
    constexpr int ITA = (BM * 8) / 256;   // float4 staging iters for A
    constexpr int ITB = (BN * 8) / 256;

    __shared__ uint32_t As[BM][36];
    __shared__ uint32_t Bs[BN][36];

    const int tid = threadIdx.x;
    const int wid = tid >> 5;
    const int lane = tid & 31;
    const int lr = lane >> 2;     // 0..7
    const int lc = lane & 3;      // 0..3
    const int warpM = wid % WARPS_M;
    const int warpN = wid / WARPS_M;
    const int m0 = blockIdx.y * BM;
    const int n0 = blockIdx.x * BN;

    float acc[MF][NF][4];
#pragma unroll
    for (int i = 0; i < MF; i++)
#pragma unroll
        for (int j = 0; j < NF; j++)
#pragma unroll
            for (int q = 0; q < 4; q++) acc[i][j][q] = 0.f;

    float4 ra[ITA], rb[ITB];
    const int ktiles = K / BK;

    // Prologue: stage tile 0
#pragma unroll
    for (int i = 0; i < ITA; i++) {
        int idx = tid + i * 256, r = idx >> 3, c = idx & 7;
        ra[i] = *(const float4*)(A + (size_t)(m0 + r) * lda + c * 4);
    }
#pragma unroll
    for (int i = 0; i < ITB; i++) {
        int idx = tid + i * 256, r = idx >> 3, c = idx & 7;
        rb[i] = *(const float4*)(B + (size_t)(n0 + r) * ldb + c * 4);
    }
#pragma unroll
    for (int i = 0; i < ITA; i++) {
        int idx = tid + i * 256, r = idx >> 3, c = idx & 7;
        uint4 u = {tf32u(ra[i].x), tf32u(ra[i].y), tf32u(ra[i].z), tf32u(ra[i].w)};
        *(uint4*)&As[r][c * 4] = u;
    }
#pragma unroll
    for (int i = 0; i < ITB; i++) {
        int idx = tid + i * 256, r = idx >> 3, c = idx & 7;
        uint4 u = {tf32u(rb[i].x), tf32u(rb[i].y), tf32u(rb[i].z), tf32u(rb[i].w)};
        *(uint4*)&Bs[r][c * 4] = u;
    }

    for (int kt = 0; kt < ktiles; kt++) {
        __syncthreads();   // staged tile kt visible

        // Issue LDG for tile kt+1 (hide latency under compute)
        if (kt + 1 < ktiles) {
            const int k0n = (kt + 1) * BK;
#pragma unroll
            for (int i = 0; i < ITA; i++) {
                int idx = tid + i * 256, r = idx >> 3, c = idx & 7;
                ra[i] = *(const float4*)(A + (size_t)(m0 + r) * lda + k0n + c * 4);
            }
#pragma unroll
            for (int i = 0; i < ITB; i++) {
                int idx = tid + i * 256, r = idx >> 3, c = idx & 7;
                rb[i] = *(const float4*)(B + (size_t)(n0 + r) * ldb + k0n + c * 4);
            }
        }

        // Compute on smem tile
#pragma unroll
        for (int ks = 0; ks < 4; ks++) {
            const int k0 = ks * 8;
            uint32_t af[MF][4], bf[NF][2];
#pragma unroll
            for (int i = 0; i < MF; i++) {
                int r = warpM * WM + i * 16 + lr;
                af[i][0] = As[r][k0 + lc];
                af[i][1] = As[r + 8][k0 + lc];
                af[i][2] = As[r][k0 + lc + 4];
                af[i][3] = As[r + 8][k0 + lc + 4];
            }
#pragma unroll
            for (int j = 0; j < NF; j++) {
                int r = warpN * WN + j * 8 + lr;
                bf[j][0] = Bs[r][k0 + lc];
                bf[j][1] = Bs[r][k0 + lc + 4];
            }
#pragma unroll
            for (int i = 0; i < MF; i++)
#pragma unroll
                for (int j = 0; j < NF; j++)
                    mma_tf32(acc[i][j], af[i], bf[j]);
        }

        __syncthreads();   // everyone done reading tile kt

        if (kt + 1 < ktiles) {
#pragma unroll
            for (int i = 0; i < ITA; i++) {
                int idx = tid + i * 256, r = idx >> 3, c = idx & 7;
                uint4 u = {tf32u(ra[i].x), tf32u(ra[i].y), tf32u(ra[i].z), tf32u(ra[i].w)};
                *(uint4*)&As[r][c * 4] = u;
            }
#pragma unroll
            for (int i = 0; i < ITB; i++) {
                int idx = tid + i * 256, r = idx >> 3, c = idx & 7;
                uint4 u = {tf32u(rb[i].x), tf32u(rb[i].y), tf32u(rb[i].z), tf32u(rb[i].w)};
                *(uint4*)&Bs[r][c * 4] = u;
            }
        }
    }

    // Epilogue
#pragma unroll
    for (int i = 0; i < MF; i++) {
        int r0 = m0 + warpM * WM + i * 16 + lr;
#pragma unroll
        for (int j = 0; j < NF; j++) {
            int c0 = n0 + warpN * WN + j * 8 + 2 * lc;
            float2 bv = bias ? *(const float2*)(bias + c0) : make_float2(0.f, 0.f);
            float2 v0 = {acc[i][j][0] * alpha + bv.x, acc[i][j][1] * alpha + bv.y};
            float2 v1 = {acc[i][j][2] * alpha + bv.x, acc[i][j][3] * alpha + bv.y};
            *(float2*)(C + (size_t)r0 * ldc + c0) = v0;
            *(float2*)(C + (size_t)(r0 + 8) * ldc + c0) = v1;
        }
    }
}

// ---------------- wrappers ----------------
__global__ void __launch_bounds__(256) k_proj(
    const float* __restrict__ A, const float* __restrict__ W,
    const float* __restrict__ bias, float* __restrict__ C)
{
    mm_core<128, 2, 4>(A, E_DIM, W, E_DIM, C, E_DIM, bias, 1.f, E_DIM);
}

__global__ void __launch_bounds__(256) k_scores(
    const float* __restrict__ q, const float* __restrict__ k, float* __restrict__ sc)
{
    int z = blockIdx.z;
    int b = z >> 4, h = z & 15;
    const float* A = q + (size_t)b * E_DIM + h * HD_DIM;
    const float* B = k + (size_t)b * E_DIM + h * HD_DIM;
    float* C = sc + (size_t)z * T_DIM * S_DIM;
    mm_core<128, 2, 4>(A, LDQ, B, LDQ, C, S_DIM, nullptr, 0.125f, HD_DIM);
}

__global__ void __launch_bounds__(256) k_av(
    const float* __restrict__ attn, const float* __restrict__ vt, float* __restrict__ ctx)
{
    int z = blockIdx.z;
    int b = z >> 4, h = z & 15;
    const float* A = attn + (size_t)z * T_DIM * S_DIM;
    const float* B = vt + (size_t)z * HD_DIM * S_DIM;
    float* C = ctx + (size_t)b * E_DIM + h * HD_DIM;
    mm_core<64, 4, 2>(A, S_DIM, B, S_DIM, C, LDQ, nullptr, 1.f, S_DIM);
}

// V transpose: vt[(z*64+d)*S + s] = v[(s*2+b)*E + h*64+d]
__global__ void __launch_bounds__(256) k_transpose_v(
    const float* __restrict__ v, float* __restrict__ vt)
{
    __shared__ float t[32][33];
    int z = blockIdx.z, b = z >> 4, h = z & 15;
    int s0 = blockIdx.x * 32, d0 = blockIdx.y * 32;
    int lx = threadIdx.x & 31, ly = threadIdx.x >> 5;
#pragma unroll
    for (int i = 0; i < 32; i += 8) {
        int s = s0 + ly + i;
        t[ly + i][lx] = v[(size_t)(s * B_DIM + b) * E_DIM + h * HD_DIM + d0 + lx];
    }
    __syncthreads();
#pragma unroll
    for (int i = 0; i < 32; i += 8) {
        int d = d0 + ly + i;
        vt[((size_t)z * HD_DIM + d) * S_DIM + s0 + lx] = t[lx][ly + i];
    }
}

// ---------------- softmax + head-average ----------------
__global__ void __launch_bounds__(256) softmax_avg(
    float* __restrict__ scores, float* __restrict__ avgw)
{
    const int t = blockIdx.x;
    const int b = blockIdx.y;
    const int tid = threadIdx.x;
    __shared__ float red[8];

    float avg[8];
#pragma unroll
    for (int i = 0; i < 8; i++) avg[i] = 0.f;

    for (int h = 0; h < H_DIM; h++) {
        float* row = scores + (((size_t)(b * H_DIM + h)) * T_DIM + t) * S_DIM;
        float v[8];
        float m = -1e30f;
#pragma unroll
        for (int i = 0; i < 8; i++) {
            v[i] = row[tid + i * 256];
            m = fmaxf(m, v[i]);
        }
#pragma unroll
        for (int o = 16; o; o >>= 1) m = fmaxf(m, __shfl_xor_sync(0xffffffffu, m, o));
        if ((tid & 31) == 0) red[tid >> 5] = m;
        __syncthreads();
        float M = red[0];
#pragma unroll
        for (int i = 1; i < 8; i++) M = fmaxf(M, red[i]);
        __syncthreads();

        float s = 0.f;
#pragma unroll
        for (int i = 0; i < 8; i++) {
            v[i] = __expf(v[i] - M);
            s += v[i];
        }
#pragma unroll
        for (int o = 16; o; o >>= 1) s += __shfl_xor_sync(0xffffffffu, s, o);
        if ((tid & 31) == 0) red[tid >> 5] = s;
        __syncthreads();
        float Z = red[0];
#pragma unroll
        for (int i = 1; i < 8; i++) Z += red[i];
        const float inv = 1.f / Z;
#pragma unroll
        for (int i = 0; i < 8; i++) {
            v[i] *= inv;
            row[tid + i * 256] = v[i];
            avg[i] += v[i];
        }
        __syncthreads();
    }

    float* arow = avgw + ((size_t)b * T_DIM + t) * S_DIM;
    const float invH = 1.f / (float)H_DIM;
#pragma unroll
    for (int i = 0; i < 8; i++) arow[tid + i * 256] = avg[i] * invH;
}

// ---------------------------------------------------------------------------
extern "C" void kernel_launch(void* const* d_in, const int* in_sizes, int n_in,
                              void* d_out, int out_size)
{
    const float* query = (const float*)d_in[0];
    const float* key   = (const float*)d_in[1];
    const float* value = (const float*)d_in[2];
    const float* Wq = (const float*)d_in[3];
    const float* bq = (const float*)d_in[4];
    const float* Wk = (const float*)d_in[5];
    const float* bk = (const float*)d_in[6];
    const float* Wv = (const float*)d_in[7];
    const float* bv = (const float*)d_in[8];
    const float* Wo = (const float*)d_in[9];
    const float* bo = (const float*)d_in[10];

    float* out  = (float*)d_out;
    float* avgw = out + (size_t)MB_DIM * E_DIM;

    float *q, *k, *v, *vt, *ctx, *sc;
    cudaGetSymbolAddress((void**)&q,   g_q);
    cudaGetSymbolAddress((void**)&k,   g_k);
    cudaGetSymbolAddress((void**)&v,   g_v);
    cudaGetSymbolAddress((void**)&vt,  g_vt);
    cudaGetSymbolAddress((void**)&ctx, g_ctx);
    cudaGetSymbolAddress((void**)&sc,  g_scores);

    dim3 gp(E_DIM / 128, MB_DIM / 128);                 // (8, 32)
    k_proj<<<gp, 256>>>(query, Wq, bq, q);
    k_proj<<<gp, 256>>>(key,   Wk, bk, k);
    k_proj<<<gp, 256>>>(value, Wv, bv, v);

    dim3 gt(S_DIM / 32, HD_DIM / 32, B_DIM * H_DIM);    // (64, 2, 32)
    k_transpose_v<<<gt, 256>>>(v, vt);

    dim3 gs(S_DIM / 128, T_DIM / 128, B_DIM * H_DIM);   // (16, 16, 32)
    k_scores<<<gs, 256>>>(q, k, sc);

    dim3 gm(T_DIM, B_DIM);                              // (2048, 2)
    softmax_avg<<<gm, 256>>>(sc, avgw);

    dim3 ga(1, T_DIM / 128, B_DIM * H_DIM);             // (1, 16, 32)
    k_av<<<ga, 256>>>(sc, vt, ctx);

    k_proj<<<gp, 256>>>(ctx, Wo, bo, out);
}

// round 4
// speedup vs baseline: 3.7319x; 1.9895x over previous
#include <cuda_runtime.h>
#include <cuda_fp16.h>
#include <cstdint>

#define T_DIM 2048
#define B_DIM 2
#define E_DIM 1024
#define H_DIM 16
#define HD_DIM 64
#define S_DIM 2048
#define MB_DIM (T_DIM * B_DIM)     // 4096
#define LDQ (B_DIM * E_DIM)        // 2048

// Static device scratch
__device__ float  g_q[(size_t)MB_DIM * E_DIM];
__device__ float  g_k[(size_t)MB_DIM * E_DIM];
__device__ float  g_v[(size_t)MB_DIM * E_DIM];
__device__ float  g_ctx[(size_t)MB_DIM * E_DIM];
__device__ float  g_scores[(size_t)B_DIM * H_DIM * T_DIM * S_DIM];
__device__ __half g_attn[(size_t)B_DIM * H_DIM * T_DIM * S_DIM];
__device__ __half g_vt[(size_t)B_DIM * H_DIM * HD_DIM * S_DIM];

__device__ __forceinline__ uint32_t smem_u32(const void* p) {
    uint32_t a;
    asm("{ .reg .u64 t; cvta.to.shared.u64 t, %1; cvt.u32.u64 %0, t; }" : "=r"(a) : "l"(p));
    return a;
}

__device__ __forceinline__ void ldm_x4(uint32_t r[4], uint32_t a) {
    asm volatile("ldmatrix.sync.aligned.m8n8.x4.shared.b16 {%0,%1,%2,%3}, [%4];"
        : "=r"(r[0]), "=r"(r[1]), "=r"(r[2]), "=r"(r[3]) : "r"(a));
}

__device__ __forceinline__ void mma_f16(float c[4], const uint32_t a[4], const uint32_t b[2]) {
    asm volatile(
        "mma.sync.aligned.m16n8k16.row.col.f32.f16.f16.f32 "
        "{%0,%1,%2,%3}, {%4,%5,%6,%7}, {%8,%9}, {%0,%1,%2,%3};"
        : "+f"(c[0]), "+f"(c[1]), "+f"(c[2]), "+f"(c[3])
        : "r"(a[0]), "r"(a[1]), "r"(a[2]), "r"(a[3]), "r"(b[0]), "r"(b[1]));
}

// ---------------------------------------------------------------------------
// fp16 mma.sync GEMM core. C[m][n] = alpha * sum_k A[m][k]*B[n][k] (+bias[n])
// BM=128, BK=32, 256 threads (8 warps), double-buffered smem, ldmatrix.
// A_F32/B_F32: operand source dtype (fp32 -> convert in staging, fp16 direct).
// ---------------------------------------------------------------------------
template <int BN, int WARPS_M, int WARPS_N, bool A_F32, bool B_F32>
__device__ __forceinline__ void mm_core(
    const void* Avp, int lda, const void* Bvp, int ldb,
    float* __restrict__ C, int ldc,
    const float* __restrict__ bias, float alpha, int K)
{
    constexpr int BM = 128, BK = 32, PAD = 40;
    constexpr int WM = BM / WARPS_M, WN = BN / WARPS_N;
    constexpr int MF = WM / 16, NF = WN / 8;
    constexpr int ITA = A_F32 ? BM / 32 : BM / 64;
    constexpr int ITB = B_F32 ? BN / 32 : BN / 64;

    __shared__ __align__(16) __half As[2][BM * PAD];
    __shared__ __align__(16) __half Bs[2][BN * PAD];

    const float*  Af = (const float*)Avp;
    const __half* Ah = (const __half*)Avp;
    const float*  Bf = (const float*)Bvp;
    const __half* Bh = (const __half*)Bvp;

    const int tid = threadIdx.x;
    const int wid = tid >> 5;
    const int lane = tid & 31;
    const int lr = lane >> 2;
    const int lc = lane & 3;
    const int warpM = wid % WARPS_M;
    const int warpN = wid / WARPS_M;
    const int m0 = blockIdx.y * BM;
    const int n0 = blockIdx.x * BN;

    const uint32_t as_base = smem_u32(&As[0][0]);
    const uint32_t bs_base = smem_u32(&Bs[0][0]);

    float acc[MF][NF][4];
#pragma unroll
    for (int i = 0; i < MF; i++)
#pragma unroll
        for (int j = 0; j < NF; j++)
#pragma unroll
            for (int q = 0; q < 4; q++) acc[i][j][q] = 0.f;

    float4 raf[A_F32 ? ITA : 1];
    uint4  rah[A_F32 ? 1 : ITA];
    float4 rbf[B_F32 ? ITB : 1];
    uint4  rbh[B_F32 ? 1 : ITB];

    auto ldgA = [&](int kt) {
        const int k0 = kt * BK;
        if constexpr (A_F32) {
#pragma unroll
            for (int i = 0; i < ITA; i++) {
                int idx = tid + i * 256, r = idx >> 3, c = (idx & 7) * 4;
                raf[i] = *(const float4*)(Af + (size_t)(m0 + r) * lda + k0 + c);
            }
        } else {
#pragma unroll
            for (int i = 0; i < ITA; i++) {
                int idx = tid + i * 256, r = idx >> 2, c = (idx & 3) * 8;
                rah[i] = *(const uint4*)(Ah + (size_t)(m0 + r) * lda + k0 + c);
            }
        }
    };
    auto ldgB = [&](int kt) {
        const int k0 = kt * BK;
        if constexpr (B_F32) {
#pragma unroll
            for (int i = 0; i < ITB; i++) {
                int idx = tid + i * 256, r = idx >> 3, c = (idx & 7) * 4;
                rbf[i] = *(const float4*)(Bf + (size_t)(n0 + r) * ldb + k0 + c);
            }
        } else {
#pragma unroll
            for (int i = 0; i < ITB; i++) {
                int idx = tid + i * 256, r = idx >> 2, c = (idx & 3) * 8;
                rbh[i] = *(const uint4*)(Bh + (size_t)(n0 + r) * ldb + k0 + c);
            }
        }
    };
    auto stsA = [&](int p) {
        if constexpr (A_F32) {
#pragma unroll
            for (int i = 0; i < ITA; i++) {
                int idx = tid + i * 256, r = idx >> 3, c = (idx & 7) * 4;
                __half2 h0 = __floats2half2_rn(raf[i].x, raf[i].y);
                __half2 h1 = __floats2half2_rn(raf[i].z, raf[i].w);
                __half2* d = (__half2*)&As[p][r * PAD + c];
                d[0] = h0; d[1] = h1;
            }
        } else {
#pragma unroll
            for (int i = 0; i < ITA; i++) {
                int idx = tid + i * 256, r = idx >> 2, c = (idx & 3) * 8;
                *(uint4*)&As[p][r * PAD + c] = rah[i];
            }
        }
    };
    auto stsB = [&](int p) {
        if constexpr (B_F32) {
#pragma unroll
            for (int i = 0; i < ITB; i++) {
                int idx = tid + i * 256, r = idx >> 3, c = (idx & 7) * 4;
                __half2 h0 = __floats2half2_rn(rbf[i].x, rbf[i].y);
                __half2 h1 = __floats2half2_rn(rbf[i].z, rbf[i].w);
                __half2* d = (__half2*)&Bs[p][r * PAD + c];
                d[0] = h0; d[1] = h1;
            }
        } else {
#pragma unroll
            for (int i = 0; i < ITB; i++) {
                int idx = tid + i * 256, r = idx >> 2, c = (idx & 3) * 8;
                *(uint4*)&Bs[p][r * PAD + c] = rbh[i];
            }
        }
    };

    auto compute = [&](int p) {
#pragma unroll
        for (int ks = 0; ks < 2; ks++) {
            const int kh = ks * 16;
            uint32_t af[MF][4], bf[NF][2];
#pragma unroll
            for (int i = 0; i < MF; i++) {
                uint32_t off = (uint32_t)((warpM * WM + i * 16 + (lane & 15)) * PAD +
                                          kh + ((lane >> 4) << 3));
                ldm_x4(af[i], as_base + (uint32_t)p * (BM * PAD * 2) + (off << 1));
            }
#pragma unroll
            for (int j = 0; j < NF; j += 2) {
                int row = warpN * WN + (j + (lane >> 4)) * 8 + (lane & 7);
                int col = kh + ((lane >> 3) & 1) * 8;
                uint32_t r4[4];
                ldm_x4(r4, bs_base + (uint32_t)p * (BN * PAD * 2) +
                           ((uint32_t)(row * PAD + col) << 1));
                bf[j][0] = r4[0]; bf[j][1] = r4[1];
                bf[j + 1][0] = r4[2]; bf[j + 1][1] = r4[3];
            }
#pragma unroll
            for (int i = 0; i < MF; i++)
#pragma unroll
                for (int j = 0; j < NF; j++)
                    mma_f16(acc[i][j], af[i], bf[j]);
        }
    };

    // Prologue: stage tile 0 into buffer 0
    ldgA(0); ldgB(0);
    stsA(0); stsB(0);

    const int ktiles = K / BK;
    for (int kt = 0; kt < ktiles; kt++) {
        __syncthreads();
        if (kt + 1 < ktiles) { ldgA(kt + 1); ldgB(kt + 1); }
        compute(kt & 1);
        if (kt + 1 < ktiles) { stsA((kt + 1) & 1); stsB((kt + 1) & 1); }
    }

    // Epilogue
#pragma unroll
    for (int i = 0; i < MF; i++) {
        int r0 = m0 + warpM * WM + i * 16 + lr;
#pragma unroll
        for (int j = 0; j < NF; j++) {
            int c0 = n0 + warpN * WN + j * 8 + 2 * lc;
            float2 bv = bias ? *(const float2*)(bias + c0) : make_float2(0.f, 0.f);
            float2 v0 = {acc[i][j][0] * alpha + bv.x, acc[i][j][1] * alpha + bv.y};
            float2 v1 = {acc[i][j][2] * alpha + bv.x, acc[i][j][3] * alpha + bv.y};
            *(float2*)(C + (size_t)r0 * ldc + c0) = v0;
            *(float2*)(C + (size_t)(r0 + 8) * ldc + c0) = v1;
        }
    }
}

// ---------------- wrappers ----------------
__global__ void __launch_bounds__(256) k_proj(
    const float* __restrict__ A, const float* __restrict__ W,
    const float* __restrict__ bias, float* __restrict__ C)
{
    mm_core<128, 2, 4, true, true>(A, E_DIM, W, E_DIM, C, E_DIM, bias, 1.f, E_DIM);
}

__global__ void __launch_bounds__(256) k_scores(
    const float* __restrict__ q, const float* __restrict__ k, float* __restrict__ sc)
{
    int z = blockIdx.z;
    int b = z >> 4, h = z & 15;
    const float* A = q + (size_t)b * E_DIM + h * HD_DIM;
    const float* B = k + (size_t)b * E_DIM + h * HD_DIM;
    float* C = sc + (size_t)z * T_DIM * S_DIM;
    mm_core<128, 2, 4, true, true>(A, LDQ, B, LDQ, C, S_DIM, nullptr, 0.125f, HD_DIM);
}

__global__ void __launch_bounds__(256) k_av(
    const __half* __restrict__ attn, const __half* __restrict__ vt, float* __restrict__ ctx)
{
    int z = blockIdx.z;
    int b = z >> 4, h = z & 15;
    const __half* A = attn + (size_t)z * T_DIM * S_DIM;
    const __half* B = vt + (size_t)z * HD_DIM * S_DIM;
    float* C = ctx + (size_t)b * E_DIM + h * HD_DIM;
    mm_core<64, 4, 2, false, false>(A, S_DIM, B, S_DIM, C, LDQ, nullptr, 1.f, S_DIM);
}

// V transpose to fp16: vt[(z*64+d)*S + s] = (half) v[(s*2+b)*E + h*64+d]
__global__ void __launch_bounds__(256) k_transpose_v(
    const float* __restrict__ v, __half* __restrict__ vt)
{
    __shared__ float t[32][33];
    int z = blockIdx.z, b = z >> 4, h = z & 15;
    int s0 = blockIdx.x * 32, d0 = blockIdx.y * 32;
    int lx = threadIdx.x & 31, ly = threadIdx.x >> 5;
#pragma unroll
    for (int i = 0; i < 32; i += 8) {
        int s = s0 + ly + i;
        t[ly + i][lx] = v[(size_t)(s * B_DIM + b) * E_DIM + h * HD_DIM + d0 + lx];
    }
    __syncthreads();
#pragma unroll
    for (int i = 0; i < 32; i += 8) {
        int d = d0 + ly + i;
        vt[((size_t)z * HD_DIM + d) * S_DIM + s0 + lx] = __float2half_rn(t[lx][ly + i]);
    }
}

// ---------------- softmax + head-average (reads fp32 scores, writes fp16 attn) --
__global__ void __launch_bounds__(256) softmax_avg(
    const float* __restrict__ scores, __half* __restrict__ attn,
    float* __restrict__ avgw)
{
    const int t = blockIdx.x;
    const int b = blockIdx.y;
    const int tid = threadIdx.x;
    __shared__ float red[8];

    float avg[8];
#pragma unroll
    for (int i = 0; i < 8; i++) avg[i] = 0.f;

    for (int h = 0; h < H_DIM; h++) {
        const size_t roff = (((size_t)(b * H_DIM + h)) * T_DIM + t) * S_DIM;
        const float* row = scores + roff;
        __half* orow = attn + roff;
        float v[8];
        float m = -1e30f;
#pragma unroll
        for (int i = 0; i < 8; i++) {
            v[i] = row[tid + i * 256];
            m = fmaxf(m, v[i]);
        }
#pragma unroll
        for (int o = 16; o; o >>= 1) m = fmaxf(m, __shfl_xor_sync(0xffffffffu, m, o));
        if ((tid & 31) == 0) red[tid >> 5] = m;
        __syncthreads();
        float M = red[0];
#pragma unroll
        for (int i = 1; i < 8; i++) M = fmaxf(M, red[i]);
        __syncthreads();

        float s = 0.f;
#pragma unroll
        for (int i = 0; i < 8; i++) {
            v[i] = __expf(v[i] - M);
            s += v[i];
        }
#pragma unroll
        for (int o = 16; o; o >>= 1) s += __shfl_xor_sync(0xffffffffu, s, o);
        if ((tid & 31) == 0) red[tid >> 5] = s;
        __syncthreads();
        float Z = red[0];
#pragma unroll
        for (int i = 1; i < 8; i++) Z += red[i];
        const float inv = 1.f / Z;
#pragma unroll
        for (int i = 0; i < 8; i++) {
            v[i] *= inv;
            orow[tid + i * 256] = __float2half_rn(v[i]);
            avg[i] += v[i];
        }
        __syncthreads();
    }

    float* arow = avgw + ((size_t)b * T_DIM + t) * S_DIM;
    const float invH = 1.f / (float)H_DIM;
#pragma unroll
    for (int i = 0; i < 8; i++) arow[tid + i * 256] = avg[i] * invH;
}

// ---------------------------------------------------------------------------
extern "C" void kernel_launch(void* const* d_in, const int* in_sizes, int n_in,
                              void* d_out, int out_size)
{
    const float* query = (const float*)d_in[0];
    const float* key   = (const float*)d_in[1];
    const float* value = (const float*)d_in[2];
    const float* Wq = (const float*)d_in[3];
    const float* bq = (const float*)d_in[4];
    const float* Wk = (const float*)d_in[5];
    const float* bk = (const float*)d_in[6];
    const float* Wv = (const float*)d_in[7];
    const float* bv = (const float*)d_in[8];
    const float* Wo = (const float*)d_in[9];
    const float* bo = (const float*)d_in[10];

    float* out  = (float*)d_out;
    float* avgw = out + (size_t)MB_DIM * E_DIM;

    float *q, *k, *v, *ctx, *sc;
    __half *attn, *vt;
    cudaGetSymbolAddress((void**)&q,    g_q);
    cudaGetSymbolAddress((void**)&k,    g_k);
    cudaGetSymbolAddress((void**)&v,    g_v);
    cudaGetSymbolAddress((void**)&ctx,  g_ctx);
    cudaGetSymbolAddress((void**)&sc,   g_scores);
    cudaGetSymbolAddress((void**)&attn, g_attn);
    cudaGetSymbolAddress((void**)&vt,   g_vt);

    dim3 gp(E_DIM / 128, MB_DIM / 128);                 // (8, 32)
    k_proj<<<gp, 256>>>(query, Wq, bq, q);
    k_proj<<<gp, 256>>>(key,   Wk, bk, k);
    k_proj<<<gp, 256>>>(value, Wv, bv, v);

    dim3 gt(S_DIM / 32, HD_DIM / 32, B_DIM * H_DIM);    // (64, 2, 32)
    k_transpose_v<<<gt, 256>>>(v, vt);

    dim3 gs(S_DIM / 128, T_DIM / 128, B_DIM * H_DIM);   // (16, 16, 32)
    k_scores<<<gs, 256>>>(q, k, sc);

    dim3 gm(T_DIM, B_DIM);                              // (2048, 2)
    softmax_avg<<<gm, 256>>>(sc, attn, avgw);

    dim3 ga(1, T_DIM / 128, B_DIM * H_DIM);             // (1, 16, 32)
    k_av<<<ga, 256>>>(attn, vt, ctx);

    k_proj<<<gp, 256>>>(ctx, Wo, bo, out);
}

// round 5
// speedup vs baseline: 4.6231x; 1.2388x over previous
#include <cuda_runtime.h>
#include <cuda_fp16.h>
#include <cstdint>

#define T_DIM 2048
#define B_DIM 2
#define E_DIM 1024
#define H_DIM 16
#define HD_DIM 64
#define S_DIM 2048
#define MB_DIM (T_DIM * B_DIM)     // 4096
#define LDQ (B_DIM * E_DIM)        // 2048

// Static device scratch (fp16 everywhere except scores/avgw)
__device__ __half g_xq[(size_t)MB_DIM * E_DIM];
__device__ __half g_xk[(size_t)MB_DIM * E_DIM];
__device__ __half g_xv[(size_t)MB_DIM * E_DIM];
__device__ __half g_wq[(size_t)E_DIM * E_DIM];
__device__ __half g_wk[(size_t)E_DIM * E_DIM];
__device__ __half g_wv[(size_t)E_DIM * E_DIM];
__device__ __half g_wo[(size_t)E_DIM * E_DIM];
__device__ __half g_qh[(size_t)MB_DIM * E_DIM];
__device__ __half g_kh[(size_t)MB_DIM * E_DIM];
__device__ __half g_vh[(size_t)MB_DIM * E_DIM];
__device__ __half g_ctxh[(size_t)MB_DIM * E_DIM];
__device__ __half g_vt[(size_t)B_DIM * H_DIM * HD_DIM * S_DIM];
__device__ float  g_scores[(size_t)B_DIM * H_DIM * T_DIM * S_DIM];
__device__ __half g_attn[(size_t)B_DIM * H_DIM * T_DIM * S_DIM];

__device__ __forceinline__ uint32_t smem_u32(const void* p) {
    uint32_t a;
    asm("{ .reg .u64 t; cvta.to.shared.u64 t, %1; cvt.u32.u64 %0, t; }" : "=r"(a) : "l"(p));
    return a;
}
__device__ __forceinline__ void cp16(uint32_t dst, const void* src) {
    asm volatile("cp.async.ca.shared.global [%0], [%1], 16;" :: "r"(dst), "l"(src) : "memory");
}
#define CP_COMMIT() asm volatile("cp.async.commit_group;" ::: "memory")
#define CP_WAIT1()  asm volatile("cp.async.wait_group 1;" ::: "memory")

__device__ __forceinline__ void ldm_x4(uint32_t r[4], uint32_t a) {
    asm volatile("ldmatrix.sync.aligned.m8n8.x4.shared.b16 {%0,%1,%2,%3}, [%4];"
        : "=r"(r[0]), "=r"(r[1]), "=r"(r[2]), "=r"(r[3]) : "r"(a));
}
__device__ __forceinline__ void mma_f16(float c[4], const uint32_t a[4], const uint32_t b[2]) {
    asm volatile(
        "mma.sync.aligned.m16n8k16.row.col.f32.f16.f16.f32 "
        "{%0,%1,%2,%3}, {%4,%5,%6,%7}, {%8,%9}, {%0,%1,%2,%3};"
        : "+f"(c[0]), "+f"(c[1]), "+f"(c[2]), "+f"(c[3])
        : "r"(a[0]), "r"(a[1]), "r"(a[2]), "r"(a[3]), "r"(b[0]), "r"(b[1]));
}

// ---------------------------------------------------------------------------
// fp16 mma.sync GEMM core, all-fp16 operands, cp.async double buffer.
// C[m][n] = alpha * sum_k A[m][k]*B[n][k] (+bias[n]).  BM=128, BK=64.
// ---------------------------------------------------------------------------
template <int BN, int WARPS_M, int WARPS_N, bool C_HALF>
__device__ __forceinline__ void mm_core(
    const __half* __restrict__ A, int lda,
    const __half* __restrict__ B, int ldb,
    void* Cp, int ldc,
    const float* __restrict__ bias, float alpha, int K)
{
    constexpr int BM = 128, BK = 64, PAD = 72;
    constexpr int WM = BM / WARPS_M, WN = BN / WARPS_N;
    constexpr int MF = WM / 16, NF = WN / 8;
    constexpr int NCA = (BM * BK / 8) / 256;   // 16B chunks per thread for A
    constexpr int NCB = (BN * BK / 8) / 256;
    constexpr uint32_t ASTG = BM * PAD * 2;    // bytes per A stage
    constexpr uint32_t BSTG = BN * PAD * 2;

    extern __shared__ __align__(16) char dsm[];
    __half* As = (__half*)dsm;                     // [2][BM*PAD]
    __half* Bs = (__half*)(dsm + 2 * ASTG);        // [2][BN*PAD]

    const int tid = threadIdx.x;
    const int wid = tid >> 5;
    const int lane = tid & 31;
    const int lr = lane >> 2;
    const int lc = lane & 3;
    const int warpM = wid % WARPS_M;
    const int warpN = wid / WARPS_M;
    const int m0 = blockIdx.y * BM;
    const int n0 = blockIdx.x * BN;

    const uint32_t as_base = smem_u32(As);
    const uint32_t bs_base = smem_u32(Bs);

    float acc[MF][NF][4];
#pragma unroll
    for (int i = 0; i < MF; i++)
#pragma unroll
        for (int j = 0; j < NF; j++)
#pragma unroll
            for (int q = 0; q < 4; q++) acc[i][j][q] = 0.f;

    auto ldgsts = [&](int kt, int p) {
        const int k0 = kt * BK;
#pragma unroll
        for (int i = 0; i < NCA; i++) {
            int ch = tid + i * 256, r = ch >> 3, c = (ch & 7) * 8;
            cp16(as_base + p * ASTG + (uint32_t)(r * PAD + c) * 2,
                 A + (size_t)(m0 + r) * lda + k0 + c);
        }
#pragma unroll
        for (int i = 0; i < NCB; i++) {
            int ch = tid + i * 256, r = ch >> 3, c = (ch & 7) * 8;
            cp16(bs_base + p * BSTG + (uint32_t)(r * PAD + c) * 2,
                 B + (size_t)(n0 + r) * ldb + k0 + c);
        }
    };

    auto compute = [&](int p) {
        const uint32_t ab = as_base + p * ASTG;
        const uint32_t bb = bs_base + p * BSTG;
#pragma unroll
        for (int ks = 0; ks < BK / 16; ks++) {
            const int kh = ks * 16;
            uint32_t af[MF][4], bf[NF][2];
#pragma unroll
            for (int i = 0; i < MF; i++) {
                uint32_t off = (uint32_t)((warpM * WM + i * 16 + (lane & 15)) * PAD +
                                          kh + ((lane >> 4) << 3));
                ldm_x4(af[i], ab + (off << 1));
            }
#pragma unroll
            for (int j = 0; j < NF; j += 2) {
                int row = warpN * WN + (j + (lane >> 4)) * 8 + (lane & 7);
                int col = kh + ((lane >> 3) & 1) * 8;
                uint32_t r4[4];
                ldm_x4(r4, bb + ((uint32_t)(row * PAD + col) << 1));
                bf[j][0] = r4[0]; bf[j][1] = r4[1];
                bf[j + 1][0] = r4[2]; bf[j + 1][1] = r4[3];
            }
#pragma unroll
            for (int i = 0; i < MF; i++)
#pragma unroll
                for (int j = 0; j < NF; j++)
                    mma_f16(acc[i][j], af[i], bf[j]);
        }
    };

    // Pipeline: 2-stage cp.async double buffer
    ldgsts(0, 0);
    CP_COMMIT();
    const int ktiles = K / BK;
    for (int kt = 0; kt < ktiles; kt++) {
        if (kt + 1 < ktiles) ldgsts(kt + 1, (kt + 1) & 1);
        CP_COMMIT();
        CP_WAIT1();
        __syncthreads();
        compute(kt & 1);
        __syncthreads();
    }

    // Epilogue
#pragma unroll
    for (int i = 0; i < MF; i++) {
        int r0 = m0 + warpM * WM + i * 16 + lr;
#pragma unroll
        for (int j = 0; j < NF; j++) {
            int c0 = n0 + warpN * WN + j * 8 + 2 * lc;
            float2 bv = bias ? *(const float2*)(bias + c0) : make_float2(0.f, 0.f);
            float x0 = acc[i][j][0] * alpha + bv.x;
            float x1 = acc[i][j][1] * alpha + bv.y;
            float x2 = acc[i][j][2] * alpha + bv.x;
            float x3 = acc[i][j][3] * alpha + bv.y;
            if constexpr (C_HALF) {
                __half* C = (__half*)Cp;
                *(__half2*)(C + (size_t)r0 * ldc + c0) = __floats2half2_rn(x0, x1);
                *(__half2*)(C + (size_t)(r0 + 8) * ldc + c0) = __floats2half2_rn(x2, x3);
            } else {
                float* C = (float*)Cp;
                *(float2*)(C + (size_t)r0 * ldc + c0) = make_float2(x0, x1);
                *(float2*)(C + (size_t)(r0 + 8) * ldc + c0) = make_float2(x2, x3);
            }
        }
    }
}

// ---------------- wrappers ----------------
__global__ void __launch_bounds__(256) k_proj_h(
    const __half* __restrict__ A, const __half* __restrict__ W,
    const float* __restrict__ bias, __half* __restrict__ C)
{
    mm_core<128, 2, 4, true>(A, E_DIM, W, E_DIM, C, E_DIM, bias, 1.f, E_DIM);
}

__global__ void __launch_bounds__(256) k_proj_f(
    const __half* __restrict__ A, const __half* __restrict__ W,
    const float* __restrict__ bias, float* __restrict__ C)
{
    mm_core<128, 2, 4, false>(A, E_DIM, W, E_DIM, C, E_DIM, bias, 1.f, E_DIM);
}

__global__ void __launch_bounds__(256) k_scores(
    const __half* __restrict__ q, const __half* __restrict__ k, float* __restrict__ sc)
{
    int z = blockIdx.z;
    int b = z >> 4, h = z & 15;
    const __half* A = q + (size_t)b * E_DIM + h * HD_DIM;
    const __half* B = k + (size_t)b * E_DIM + h * HD_DIM;
    float* C = sc + (size_t)z * T_DIM * S_DIM;
    mm_core<128, 2, 4, false>(A, LDQ, B, LDQ, C, S_DIM, nullptr, 0.125f, HD_DIM);
}

__global__ void __launch_bounds__(256) k_av(
    const __half* __restrict__ attn, const __half* __restrict__ vt, __half* __restrict__ ctx)
{
    int z = blockIdx.z;
    int b = z >> 4, h = z & 15;
    const __half* A = attn + (size_t)z * T_DIM * S_DIM;
    const __half* B = vt + (size_t)z * HD_DIM * S_DIM;
    __half* C = ctx + (size_t)b * E_DIM + h * HD_DIM;
    mm_core<64, 4, 2, true>(A, S_DIM, B, S_DIM, C, LDQ, nullptr, 1.f, S_DIM);
}

// fp32 -> fp16 convert (n % 4 == 0)
__global__ void __launch_bounds__(256) k_cvt(
    const float* __restrict__ x, __half* __restrict__ y, int n)
{
    int i = (blockIdx.x * 256 + threadIdx.x) * 4;
    if (i < n) {
        float4 v = *(const float4*)(x + i);
        __half2 a = __floats2half2_rn(v.x, v.y);
        __half2 b = __floats2half2_rn(v.z, v.w);
        union { __half2 h[2]; uint2 u; } p;
        p.h[0] = a; p.h[1] = b;
        *(uint2*)(y + i) = p.u;
    }
}

// V transpose fp16: vt[(z*64+d)*S + s] = vh[(s*2+b)*E + h*64+d]
__global__ void __launch_bounds__(256) k_transpose_v(
    const __half* __restrict__ v, __half* __restrict__ vt)
{
    __shared__ __half t[32][34];
    int z = blockIdx.z, b = z >> 4, h = z & 15;
    int s0 = blockIdx.x * 32, d0 = blockIdx.y * 32;
    int lx = threadIdx.x & 31, ly = threadIdx.x >> 5;
#pragma unroll
    for (int i = 0; i < 32; i += 8) {
        int s = s0 + ly + i;
        t[ly + i][lx] = v[(size_t)(s * B_DIM + b) * E_DIM + h * HD_DIM + d0 + lx];
    }
    __syncthreads();
#pragma unroll
    for (int i = 0; i < 32; i += 8) {
        int d = d0 + ly + i;
        vt[((size_t)z * HD_DIM + d) * S_DIM + s0 + lx] = t[lx][ly + i];
    }
}

// ---------------- softmax + head-average ----------------
__global__ void __launch_bounds__(256) softmax_avg(
    const float* __restrict__ scores, __half* __restrict__ attn,
    float* __restrict__ avgw)
{
    const int t = blockIdx.x;
    const int b = blockIdx.y;
    const int tid = threadIdx.x;
    __shared__ float red[8];

    float avg[8];
#pragma unroll
    for (int i = 0; i < 8; i++) avg[i] = 0.f;

    for (int h = 0; h < H_DIM; h++) {
        const size_t roff = (((size_t)(b * H_DIM + h)) * T_DIM + t) * S_DIM;
        const float* row = scores + roff;
        __half* orow = attn + roff;
        float v[8];
        float m = -1e30f;
#pragma unroll
        for (int i = 0; i < 8; i++) {
            v[i] = row[tid + i * 256];
            m = fmaxf(m, v[i]);
        }
#pragma unroll
        for (int o = 16; o; o >>= 1) m = fmaxf(m, __shfl_xor_sync(0xffffffffu, m, o));
        if ((tid & 31) == 0) red[tid >> 5] = m;
        __syncthreads();
        float M = red[0];
#pragma unroll
        for (int i = 1; i < 8; i++) M = fmaxf(M, red[i]);
        __syncthreads();

        float s = 0.f;
#pragma unroll
        for (int i = 0; i < 8; i++) {
            v[i] = __expf(v[i] - M);
            s += v[i];
        }
#pragma unroll
        for (int o = 16; o; o >>= 1) s += __shfl_xor_sync(0xffffffffu, s, o);
        if ((tid & 31) == 0) red[tid >> 5] = s;
        __syncthreads();
        float Z = red[0];
#pragma unroll
        for (int i = 1; i < 8; i++) Z += red[i];
        const float inv = 1.f / Z;
#pragma unroll
        for (int i = 0; i < 8; i++) {
            v[i] *= inv;
            orow[tid + i * 256] = __float2half_rn(v[i]);
            avg[i] += v[i];
        }
        __syncthreads();
    }

    float* arow = avgw + ((size_t)b * T_DIM + t) * S_DIM;
    const float invH = 1.f / (float)H_DIM;
#pragma unroll
    for (int i = 0; i < 8; i++) arow[tid + i * 256] = avg[i] * invH;
}

// ---------------------------------------------------------------------------
extern "C" void kernel_launch(void* const* d_in, const int* in_sizes, int n_in,
                              void* d_out, int out_size)
{
    const float* query = (const float*)d_in[0];
    const float* key   = (const float*)d_in[1];
    const float* value = (const float*)d_in[2];
    const float* Wq = (const float*)d_in[3];
    const float* bq = (const float*)d_in[4];
    const float* Wk = (const float*)d_in[5];
    const float* bk = (const float*)d_in[6];
    const float* Wv = (const float*)d_in[7];
    const float* bv = (const float*)d_in[8];
    const float* Wo = (const float*)d_in[9];
    const float* bo = (const float*)d_in[10];

    float* out  = (float*)d_out;
    float* avgw = out + (size_t)MB_DIM * E_DIM;

    __half *xq, *xk, *xv, *wq, *wk, *wv, *wo, *qh, *kh, *vh, *ctxh, *vt, *attn;
    float *sc;
    cudaGetSymbolAddress((void**)&xq,   g_xq);
    cudaGetSymbolAddress((void**)&xk,   g_xk);
    cudaGetSymbolAddress((void**)&xv,   g_xv);
    cudaGetSymbolAddress((void**)&wq,   g_wq);
    cudaGetSymbolAddress((void**)&wk,   g_wk);
    cudaGetSymbolAddress((void**)&wv,   g_wv);
    cudaGetSymbolAddress((void**)&wo,   g_wo);
    cudaGetSymbolAddress((void**)&qh,   g_qh);
    cudaGetSymbolAddress((void**)&kh,   g_kh);
    cudaGetSymbolAddress((void**)&vh,   g_vh);
    cudaGetSymbolAddress((void**)&ctxh, g_ctxh);
    cudaGetSymbolAddress((void**)&vt,   g_vt);
    cudaGetSymbolAddress((void**)&attn, g_attn);
    cudaGetSymbolAddress((void**)&sc,   g_scores);

    const int SM_BIG = 2 * (128 * 72 * 2) * 2;            // 73728
    const int SM_AV  = 2 * (128 * 72 * 2) + 2 * (64 * 72 * 2);  // 55296
    cudaFuncSetAttribute(k_proj_h, cudaFuncAttributeMaxDynamicSharedMemorySize, SM_BIG);
    cudaFuncSetAttribute(k_proj_f, cudaFuncAttributeMaxDynamicSharedMemorySize, SM_BIG);
    cudaFuncSetAttribute(k_scores, cudaFuncAttributeMaxDynamicSharedMemorySize, SM_BIG);
    cudaFuncSetAttribute(k_av,     cudaFuncAttributeMaxDynamicSharedMemorySize, SM_AV);

    const int NXE = MB_DIM * E_DIM;   // 4M
    const int NWW = E_DIM * E_DIM;    // 1M
    k_cvt<<<NXE / 1024, 256>>>(query, xq, NXE);
    k_cvt<<<NXE / 1024, 256>>>(key,   xk, NXE);
    k_cvt<<<NXE / 1024, 256>>>(value, xv, NXE);
    k_cvt<<<NWW / 1024, 256>>>(Wq, wq, NWW);
    k_cvt<<<NWW / 1024, 256>>>(Wk, wk, NWW);
    k_cvt<<<NWW / 1024, 256>>>(Wv, wv, NWW);
    k_cvt<<<NWW / 1024, 256>>>(Wo, wo, NWW);

    dim3 gp(E_DIM / 128, MB_DIM / 128);                 // (8, 32)
    k_proj_h<<<gp, 256, SM_BIG>>>(xq, wq, bq, qh);
    k_proj_h<<<gp, 256, SM_BIG>>>(xk, wk, bk, kh);
    k_proj_h<<<gp, 256, SM_BIG>>>(xv, wv, bv, vh);

    dim3 gt(S_DIM / 32, HD_DIM / 32, B_DIM * H_DIM);    // (64, 2, 32)
    k_transpose_v<<<gt, 256>>>(vh, vt);

    dim3 gs(S_DIM / 128, T_DIM / 128, B_DIM * H_DIM);   // (16, 16, 32)
    k_scores<<<gs, 256, SM_BIG>>>(qh, kh, sc);

    dim3 gm(T_DIM, B_DIM);                              // (2048, 2)
    softmax_avg<<<gm, 256>>>(sc, attn, avgw);

    dim3 ga(1, T_DIM / 128, B_DIM * H_DIM);             // (1, 16, 32)
    k_av<<<ga, 256, SM_AV>>>(attn, vt, ctxh);

    k_proj_f<<<gp, 256, SM_BIG>>>(ctxh, wo, bo, out);
}